// round 8
// baseline (speedup 1.0000x reference)
#include <cuda_runtime.h>
#include <cuda_bf16.h>
#include <cuda_fp8.h>
#include <cstdint>

#define NB 4096
#define N2 8192
#define DD 256
#define INV_TEMP 2.0f
#define FP8_SCALE 16.0f
#define EPI_SCALE (INV_TEMP / (FP8_SCALE * FP8_SCALE))   // 2/256

#define BM 128
#define BN 128
#define BKB 128                  // k-chunk in fp8 elements (=bytes)
#define NCHUNK (DD / BKB)        // 2 chunks
#define NSTRIPE (N2 / BN)        // 64 column stripes
#define NTILE 64
#define NTRI (NTILE * (NTILE + 1) / 2)   // 2080
#define PADB 144                 // bytes per smem row (128 data + 16 pad)

// Scratch (static device globals — no allocation)
__device__ __nv_fp8_storage_t g_z8[(size_t)N2 * DD]; // normalized rows, fp8 e4m3, x16
__device__ __nv_bfloat16  g_zb[(size_t)N2 * DD];     // normalized rows bf16 (for pos pairs)
__device__ float          g_partial[NSTRIPE * N2];   // per-stripe row sums of exp(sim)
__device__ float          g_loss[N2];
__device__ int            g_sem;

__device__ __forceinline__ uint32_t smem_u32(const void* p) {
    return (uint32_t)__cvta_generic_to_shared(p);
}

__device__ __forceinline__ void ldsm_x4(uint32_t addr, uint32_t& r0, uint32_t& r1,
                                        uint32_t& r2, uint32_t& r3) {
    asm volatile("ldmatrix.sync.aligned.m8n8.x4.shared.b16 {%0,%1,%2,%3}, [%4];"
                 : "=r"(r0), "=r"(r1), "=r"(r2), "=r"(r3) : "r"(addr));
}

__device__ __forceinline__ void mma_fp8(float* d, const uint32_t* a, const uint32_t* b) {
    asm volatile(
        "mma.sync.aligned.m16n8k32.row.col.f32.e4m3.e4m3.f32 "
        "{%0,%1,%2,%3}, {%4,%5,%6,%7}, {%8,%9}, {%0,%1,%2,%3};"
        : "+f"(d[0]), "+f"(d[1]), "+f"(d[2]), "+f"(d[3])
        : "r"(a[0]), "r"(a[1]), "r"(a[2]), "r"(a[3]), "r"(b[0]), "r"(b[1]));
}

__device__ __forceinline__ void cp_async16(uint32_t smem_addr, const void* gptr) {
    asm volatile("cp.async.cg.shared.global [%0], [%1], 16;"
                 :: "r"(smem_addr), "l"(gptr) : "memory");
}
#define CP_COMMIT() asm volatile("cp.async.commit_group;" ::: "memory")
#define CP_WAIT(n)  asm volatile("cp.async.wait_group %0;" :: "n"(n) : "memory")

// ---------------------------------------------------------------------------
// Kernel 1: L2-normalize -> g_z8 (fp8 e4m3, scaled x16) + g_zb (bf16).
// ---------------------------------------------------------------------------
__global__ void k_normalize(const float* __restrict__ xi, const float* __restrict__ xj) {
    int row  = blockIdx.x * 8 + (threadIdx.x >> 5);
    int lane = threadIdx.x & 31;
    const float* src = (row < NB) ? (xi + (size_t)row * DD)
                                  : (xj + (size_t)(row - NB) * DD);
    float4 v0 = *(const float4*)(src + lane * 4);
    float4 v1 = *(const float4*)(src + 128 + lane * 4);
    float s = v0.x*v0.x + v0.y*v0.y + v0.z*v0.z + v0.w*v0.w
            + v1.x*v1.x + v1.y*v1.y + v1.z*v1.z + v1.w*v1.w;
    #pragma unroll
    for (int o = 16; o > 0; o >>= 1) s += __shfl_xor_sync(0xffffffffu, s, o);
    float inv = 1.0f / fmaxf(sqrtf(s), 1e-12f);
    v0.x *= inv; v0.y *= inv; v0.z *= inv; v0.w *= inv;
    v1.x *= inv; v1.y *= inv; v1.z *= inv; v1.w *= inv;

    // bf16 copy (positive-pair dots)
    __nv_bfloat162 b[4];
    b[0] = __floats2bfloat162_rn(v0.x, v0.y);
    b[1] = __floats2bfloat162_rn(v0.z, v0.w);
    b[2] = __floats2bfloat162_rn(v1.x, v1.y);
    b[3] = __floats2bfloat162_rn(v1.z, v1.w);
    __nv_bfloat16* db = g_zb + (size_t)row * DD;
    *(uint2*)(db + lane * 4)       = make_uint2(*(uint32_t*)&b[0], *(uint32_t*)&b[1]);
    *(uint2*)(db + 128 + lane * 4) = make_uint2(*(uint32_t*)&b[2], *(uint32_t*)&b[3]);

    // fp8 copy, scaled by 16 (elements ~1.0 rms; well inside e4m3 range)
    float2 f01 = make_float2(v0.x * FP8_SCALE, v0.y * FP8_SCALE);
    float2 f23 = make_float2(v0.z * FP8_SCALE, v0.w * FP8_SCALE);
    float2 f45 = make_float2(v1.x * FP8_SCALE, v1.y * FP8_SCALE);
    float2 f67 = make_float2(v1.z * FP8_SCALE, v1.w * FP8_SCALE);
    uint32_t p0 = (uint32_t)__nv_cvt_float2_to_fp8x2(f01, __NV_SATFINITE, __NV_E4M3)
                | ((uint32_t)__nv_cvt_float2_to_fp8x2(f23, __NV_SATFINITE, __NV_E4M3) << 16);
    uint32_t p1 = (uint32_t)__nv_cvt_float2_to_fp8x2(f45, __NV_SATFINITE, __NV_E4M3)
                | ((uint32_t)__nv_cvt_float2_to_fp8x2(f67, __NV_SATFINITE, __NV_E4M3) << 16);
    // lane covers elems [lane*4, lane*4+3] and [128+lane*4 ...]; store as two u32
    *(uint32_t*)(g_z8 + (size_t)row * DD + lane * 4)       = p0;
    *(uint32_t*)(g_z8 + (size_t)row * DD + 128 + lane * 4) = p1;
}

// ---------------------------------------------------------------------------
// Kernel 2: FP8 HMMA 128x128 tile, upper triangle, 4 warps x (64x64).
// Off-diagonal tiles emit row AND column exp-sums; diagonal: rows only.
// ---------------------------------------------------------------------------
#define CHUNK_BYTES (BM * PADB)                  // 18432 per operand buffer
#define SMEM_BYTES  (2 * 2 * CHUNK_BYTES)        // 73728

__global__ __launch_bounds__(128, 2) void k_expsum_mma() {
    extern __shared__ char smem[];
    int tid   = threadIdx.x;
    int lane  = tid & 31;
    int wid   = tid >> 5;          // 0..3
    int warpM = wid >> 1;          // 0..1
    int warpN = wid & 1;           // 0..1

    // Triangular decode: blockIdx.x -> (bi, bj), bi <= bj.
    int idx = blockIdx.x;
    int bi = (int)(64.5f - sqrtf(64.5f * 64.5f - 2.0f * (float)idx));
    while ((bi + 1) * NTILE - ((bi + 1) * bi) / 2 <= idx) ++bi;
    while (bi * NTILE - (bi * (bi - 1)) / 2 > idx) --bi;
    int bj = bi + (idx - (bi * NTILE - (bi * (bi - 1)) / 2));
    int r0 = bi * BM;
    int c0 = bj * BN;

    int lrow = tid >> 3;               // 0..15
    int lcolB = (tid & 7) * 16;        // byte col within chunk row
    uint32_t sbase = smem_u32(smem);

    auto load_chunk = [&](int kc, int b) {
        uint32_t aoff = sbase + (uint32_t)(b * 2 * CHUNK_BYTES);
        uint32_t boff = aoff + (uint32_t)CHUNK_BYTES;
        const __nv_fp8_storage_t* gA = g_z8 + (size_t)r0 * DD + kc * BKB;
        const __nv_fp8_storage_t* gB = g_z8 + (size_t)c0 * DD + kc * BKB;
        #pragma unroll
        for (int i = 0; i < 8; ++i) {
            int row = lrow + i * 16;
            cp_async16(aoff + (uint32_t)(row * PADB + lcolB),
                       gA + (size_t)row * DD + lcolB);
            cp_async16(boff + (uint32_t)(row * PADB + lcolB),
                       gB + (size_t)row * DD + lcolB);
        }
        CP_COMMIT();
    };

    // ldmatrix byte offsets within a buffer (identical pattern to bf16 case).
    uint32_t aLane[4], bLane[4];
    {
        int arow_lane = lane & 15;
        int akh       = lane >> 4;           // 16-byte half select
        #pragma unroll
        for (int m = 0; m < 4; ++m) {
            int row = warpM * 64 + m * 16 + arow_lane;
            aLane[m] = (uint32_t)(row * PADB + akh * 16);
        }
        int bn  = (lane & 7) | ((lane >> 4) << 3);
        int bkh = (lane >> 3) & 1;
        #pragma unroll
        for (int q = 0; q < 4; ++q) {
            int n = warpN * 64 + q * 16 + bn;
            bLane[q] = (uint32_t)(n * PADB + bkh * 16);
        }
    }

    float acc[4][8][4];
    #pragma unroll
    for (int m = 0; m < 4; ++m)
        #pragma unroll
        for (int q = 0; q < 8; ++q)
            #pragma unroll
            for (int e = 0; e < 4; ++e) acc[m][q][e] = 0.f;

    load_chunk(0, 0);

    #pragma unroll
    for (int kc = 0; kc < NCHUNK; ++kc) {
        if (kc + 1 < NCHUNK) { load_chunk(kc + 1, (kc + 1) & 1); CP_WAIT(1); }
        else                 { CP_WAIT(0); }
        __syncthreads();

        uint32_t abuf = sbase + (uint32_t)((kc & 1) * 2 * CHUNK_BYTES);
        uint32_t bbuf = abuf + (uint32_t)CHUNK_BYTES;

        #pragma unroll
        for (int ks = 0; ks < BKB / 32; ++ks) {     // 4 k32-steps per chunk
            uint32_t a[4][4];
            #pragma unroll
            for (int m = 0; m < 4; ++m)
                ldsm_x4(abuf + aLane[m] + ks * 32, a[m][0], a[m][1], a[m][2], a[m][3]);
            uint32_t b[8][2];
            #pragma unroll
            for (int q = 0; q < 4; ++q)
                ldsm_x4(bbuf + bLane[q] + ks * 32,
                        b[2*q][0], b[2*q][1], b[2*q+1][0], b[2*q+1][1]);
            #pragma unroll
            for (int m = 0; m < 4; ++m)
                #pragma unroll
                for (int q = 0; q < 8; ++q)
                    mma_fp8(acc[m][q], a[m], b[q]);
        }
        __syncthreads();
    }

    // --- exp in place (fold x16 scale: sim = acc/256) ---
    #pragma unroll
    for (int m = 0; m < 4; ++m)
        #pragma unroll
        for (int q = 0; q < 8; ++q)
            #pragma unroll
            for (int e = 0; e < 4; ++e)
                acc[m][q][e] = __expf(EPI_SCALE * acc[m][q][e]);

    float* rowred = (float*)smem;                 // [128][2] by warpN
    float* colred = (float*)smem + 256;           // [128][2] by warpM

    #pragma unroll
    for (int m = 0; m < 4; ++m) {
        float r0s = 0.f, r1s = 0.f;
        #pragma unroll
        for (int q = 0; q < 8; ++q) {
            r0s += acc[m][q][0] + acc[m][q][1];
            r1s += acc[m][q][2] + acc[m][q][3];
        }
        r0s += __shfl_xor_sync(0xffffffffu, r0s, 1);
        r0s += __shfl_xor_sync(0xffffffffu, r0s, 2);
        r1s += __shfl_xor_sync(0xffffffffu, r1s, 1);
        r1s += __shfl_xor_sync(0xffffffffu, r1s, 2);
        if ((lane & 3) == 0) {
            int row = warpM * 64 + m * 16 + (lane >> 2);
            rowred[row * 2 + warpN]       = r0s;
            rowred[(row + 8) * 2 + warpN] = r1s;
        }
    }

    if (bi != bj) {
        #pragma unroll
        for (int q = 0; q < 8; ++q) {
            float c0s = 0.f, c1s = 0.f;
            #pragma unroll
            for (int m = 0; m < 4; ++m) {
                c0s += acc[m][q][0] + acc[m][q][2];
                c1s += acc[m][q][1] + acc[m][q][3];
            }
            c0s += __shfl_xor_sync(0xffffffffu, c0s, 4);
            c0s += __shfl_xor_sync(0xffffffffu, c0s, 8);
            c0s += __shfl_xor_sync(0xffffffffu, c0s, 16);
            c1s += __shfl_xor_sync(0xffffffffu, c1s, 4);
            c1s += __shfl_xor_sync(0xffffffffu, c1s, 8);
            c1s += __shfl_xor_sync(0xffffffffu, c1s, 16);
            if (lane < 4) {
                int n = warpN * 64 + q * 8 + lane * 2;
                colred[n * 2 + warpM]       = c0s;
                colred[(n + 1) * 2 + warpM] = c1s;
            }
        }
    }
    __syncthreads();

    g_partial[bj * N2 + r0 + tid] = rowred[tid * 2] + rowred[tid * 2 + 1];
    if (bi != bj)
        g_partial[bi * N2 + c0 + tid] = colred[tid * 2] + colred[tid * 2 + 1];
}

// ---------------------------------------------------------------------------
// Kernel 3: per-row loss + fused mean. Diagonal term from the SAME fp8 values
// the GEMM consumed (exact cancellation); positive pair from bf16 (accurate).
// ---------------------------------------------------------------------------
__global__ void k_rowloss(float* __restrict__ out) {
    __shared__ float sm[256];
    __shared__ int isLast;
    int tid  = threadIdx.x;
    int row  = blockIdx.x * 8 + (tid >> 5);
    int lane = tid & 31;
    int partner = (row < NB) ? row + NB : row - NB;

    // ds: sum of squares of the fp8 row (raw, scaled domain)
    float ds = 0.f;
    {
        uint2 v = *(const uint2*)(g_z8 + (size_t)row * DD + lane * 8);  // 8 fp8
        uint32_t w[2] = {v.x, v.y};
        #pragma unroll
        for (int j = 0; j < 2; ++j) {
            __half2_raw h0 = __nv_cvt_fp8x2_to_halfraw2((__nv_fp8x2_storage_t)(w[j] & 0xffff), __NV_E4M3);
            __half2_raw h1 = __nv_cvt_fp8x2_to_halfraw2((__nv_fp8x2_storage_t)(w[j] >> 16), __NV_E4M3);
            float2 f0 = __half22float2(*(__half2*)&h0);
            float2 f1 = __half22float2(*(__half2*)&h1);
            ds += f0.x*f0.x + f0.y*f0.y + f1.x*f1.x + f1.y*f1.y;
        }
    }
    // dp: accurate positive-pair dot from bf16
    float dp = 0.f;
    {
        const __nv_bfloat16* zr = g_zb + (size_t)row * DD;
        const __nv_bfloat16* zp = g_zb + (size_t)partner * DD;
        uint4 av = *(const uint4*)(zr + lane * 8);
        uint4 pv = *(const uint4*)(zp + lane * 8);
        const __nv_bfloat162* ah = (const __nv_bfloat162*)&av;
        const __nv_bfloat162* ph = (const __nv_bfloat162*)&pv;
        #pragma unroll
        for (int h = 0; h < 4; ++h) {
            float2 a2 = __bfloat1622float2(ah[h]);
            float2 p2 = __bfloat1622float2(ph[h]);
            dp += a2.x * p2.x + a2.y * p2.y;
        }
    }
    #pragma unroll
    for (int o = 16; o > 0; o >>= 1) {
        ds += __shfl_xor_sync(0xffffffffu, ds, o);
        dp += __shfl_xor_sync(0xffffffffu, dp, o);
    }
    if (lane == 0) {
        float S = 0.f;
        #pragma unroll
        for (int c = 0; c < NSTRIPE; ++c) S += g_partial[c * N2 + row];
        float ed = __expf(ds * EPI_SCALE);      // matches GEMM's diagonal
        float ep = __expf(dp * INV_TEMP);
        float en = S - ed;
        g_loss[row] = -logf(ep / (ep + en));
    }
    __threadfence();
    __syncthreads();
    if (tid == 0) {
        int old = atomicAdd(&g_sem, 1);
        isLast = (old == gridDim.x - 1);
    }
    __syncthreads();
    if (isLast) {
        float s = 0.f;
        #pragma unroll
        for (int i = 0; i < 8; ++i) {
            float4 v = *(const float4*)&g_loss[(tid + i * 256) * 4];
            s += v.x + v.y + v.z + v.w;
        }
        sm[tid] = s;
        __syncthreads();
        for (int st = 128; st > 0; st >>= 1) {
            if (tid < st) sm[tid] += sm[tid + st];
            __syncthreads();
        }
        if (tid == 0) { out[0] = sm[0] * (1.0f / (float)N2); g_sem = 0; }
    }
}

extern "C" void kernel_launch(void* const* d_in, const int* in_sizes, int n_in,
                              void* d_out, int out_size) {
    const float* xi = (const float*)d_in[0];
    const float* xj = (const float*)d_in[1];
    float* out = (float*)d_out;

    cudaFuncSetAttribute(k_expsum_mma, cudaFuncAttributeMaxDynamicSharedMemorySize, SMEM_BYTES);

    k_normalize<<<N2 / 8, 256>>>(xi, xj);
    k_expsum_mma<<<NTRI, 128, SMEM_BYTES>>>();
    k_rowloss<<<N2 / 8, 256>>>(out);
}

// round 9
// speedup vs baseline: 1.3469x; 1.3469x over previous
#include <cuda_runtime.h>
#include <cuda_fp16.h>
#include <cstdint>

#define NB 4096
#define N2 8192
#define DD 256
#define INV_TEMP 2.0f

#define BM 128
#define BN 128
#define BK 64
#define NCHUNK (DD / BK)         // 4 k-chunks
#define NSTRIPE (N2 / BN)        // 64 column stripes
#define NTILE 64
#define NTRI (NTILE * (NTILE + 1) / 2)   // 2080
#define PADK 72                  // f16 elems per smem row (144B)

// Scratch (static device globals — no allocation)
__device__ __half         g_zh[(size_t)N2 * DD];     // normalized rows fp16
__device__ float          g_partial[(size_t)N2 * NSTRIPE]; // [row][stripe] exp-sums
__device__ float          g_loss[N2];
__device__ int            g_sem;

__device__ __forceinline__ uint32_t smem_u32(const void* p) {
    return (uint32_t)__cvta_generic_to_shared(p);
}

__device__ __forceinline__ void ldsm_x4(uint32_t addr, uint32_t& r0, uint32_t& r1,
                                        uint32_t& r2, uint32_t& r3) {
    asm volatile("ldmatrix.sync.aligned.m8n8.x4.shared.b16 {%0,%1,%2,%3}, [%4];"
                 : "=r"(r0), "=r"(r1), "=r"(r2), "=r"(r3) : "r"(addr));
}

// f16 inputs, f16 accumulators (packed half2 x2)
__device__ __forceinline__ void mma_f16acc(uint32_t* d, const uint32_t* a, const uint32_t* b) {
    asm volatile(
        "mma.sync.aligned.m16n8k16.row.col.f16.f16.f16.f16 "
        "{%0,%1}, {%2,%3,%4,%5}, {%6,%7}, {%0,%1};"
        : "+r"(d[0]), "+r"(d[1])
        : "r"(a[0]), "r"(a[1]), "r"(a[2]), "r"(a[3]), "r"(b[0]), "r"(b[1]));
}

__device__ __forceinline__ void cp_async16(uint32_t smem_addr, const void* gptr) {
    asm volatile("cp.async.cg.shared.global [%0], [%1], 16;"
                 :: "r"(smem_addr), "l"(gptr) : "memory");
}
#define CP_COMMIT() asm volatile("cp.async.commit_group;" ::: "memory")
#define CP_WAIT(n)  asm volatile("cp.async.wait_group %0;" :: "n"(n) : "memory")

// ---------------------------------------------------------------------------
// Kernel 1: L2-normalize rows of [x_i; x_j] -> g_zh (fp16).
// ---------------------------------------------------------------------------
__global__ void k_normalize(const float* __restrict__ xi, const float* __restrict__ xj) {
    int row  = blockIdx.x * 8 + (threadIdx.x >> 5);
    int lane = threadIdx.x & 31;
    const float* src = (row < NB) ? (xi + (size_t)row * DD)
                                  : (xj + (size_t)(row - NB) * DD);
    float4 v0 = *(const float4*)(src + lane * 4);
    float4 v1 = *(const float4*)(src + 128 + lane * 4);
    float s = v0.x*v0.x + v0.y*v0.y + v0.z*v0.z + v0.w*v0.w
            + v1.x*v1.x + v1.y*v1.y + v1.z*v1.z + v1.w*v1.w;
    #pragma unroll
    for (int o = 16; o > 0; o >>= 1) s += __shfl_xor_sync(0xffffffffu, s, o);
    float inv = 1.0f / fmaxf(sqrtf(s), 1e-12f);
    v0.x *= inv; v0.y *= inv; v0.z *= inv; v0.w *= inv;
    v1.x *= inv; v1.y *= inv; v1.z *= inv; v1.w *= inv;

    __half2 h[4];
    h[0] = __floats2half2_rn(v0.x, v0.y);
    h[1] = __floats2half2_rn(v0.z, v0.w);
    h[2] = __floats2half2_rn(v1.x, v1.y);
    h[3] = __floats2half2_rn(v1.z, v1.w);
    __half* dh = g_zh + (size_t)row * DD;
    *(uint2*)(dh + lane * 4)       = make_uint2(*(uint32_t*)&h[0], *(uint32_t*)&h[1]);
    *(uint2*)(dh + 128 + lane * 4) = make_uint2(*(uint32_t*)&h[2], *(uint32_t*)&h[3]);
}

// ---------------------------------------------------------------------------
// Kernel 2: f16-acc HMMA 128x128 tile, upper triangle, 4 warps x (64x64).
// Off-diagonal tiles emit row AND column exp-sums; diagonal: rows only.
// ---------------------------------------------------------------------------
#define CHUNK_ELEMS (BM * PADK)
#define SMEM_BYTES  (2 * 2 * CHUNK_ELEMS * 2)   // 73728 B

__global__ __launch_bounds__(128, 3) void k_expsum_mma() {
    extern __shared__ __half smem[];
    int tid   = threadIdx.x;
    int lane  = tid & 31;
    int wid   = tid >> 5;          // 0..3
    int warpM = wid >> 1;          // 0..1
    int warpN = wid & 1;           // 0..1

    // Triangular decode: blockIdx.x -> (bi, bj), bi <= bj.
    int idx = blockIdx.x;
    int bi = (int)(64.5f - sqrtf(64.5f * 64.5f - 2.0f * (float)idx));
    while ((bi + 1) * NTILE - ((bi + 1) * bi) / 2 <= idx) ++bi;
    while (bi * NTILE - (bi * (bi - 1)) / 2 > idx) --bi;
    int bj = bi + (idx - (bi * NTILE - (bi * (bi - 1)) / 2));
    int r0 = bi * BM;
    int c0 = bj * BN;

    int lrow = tid >> 3;              // 0..15
    int lcol = (tid & 7) * 8;
    uint32_t sbase = smem_u32(smem);

    auto load_chunk = [&](int kc, int b) {
        uint32_t aoff = sbase + (uint32_t)(b * 2 * CHUNK_ELEMS) * 2;
        uint32_t boff = aoff + (uint32_t)CHUNK_ELEMS * 2;
        const __half* gA = g_zh + (size_t)r0 * DD + kc * BK;
        const __half* gB = g_zh + (size_t)c0 * DD + kc * BK;
        #pragma unroll
        for (int i = 0; i < 8; ++i) {
            int row = lrow + i * 16;
            cp_async16(aoff + (uint32_t)(row * PADK + lcol) * 2,
                       gA + (size_t)row * DD + lcol);
            cp_async16(boff + (uint32_t)(row * PADK + lcol) * 2,
                       gB + (size_t)row * DD + lcol);
        }
        CP_COMMIT();
    };

    uint32_t aLane[4], bLane[4];
    {
        int arow_lane = lane & 15;
        int akh       = lane >> 4;
        #pragma unroll
        for (int m = 0; m < 4; ++m) {
            int row = warpM * 64 + m * 16 + arow_lane;
            aLane[m] = (uint32_t)(row * PADK + akh * 8) * 2;
        }
        int bn  = (lane & 7) | ((lane >> 4) << 3);
        int bkh = (lane >> 3) & 1;
        #pragma unroll
        for (int q = 0; q < 4; ++q) {
            int n = warpN * 64 + q * 16 + bn;
            bLane[q] = (uint32_t)(n * PADK + bkh * 8) * 2;
        }
    }

    uint32_t acc[4][8][2];
    #pragma unroll
    for (int m = 0; m < 4; ++m)
        #pragma unroll
        for (int q = 0; q < 8; ++q) { acc[m][q][0] = 0u; acc[m][q][1] = 0u; }

    load_chunk(0, 0);

    #pragma unroll
    for (int kc = 0; kc < NCHUNK; ++kc) {
        if (kc + 1 < NCHUNK) { load_chunk(kc + 1, (kc + 1) & 1); CP_WAIT(1); }
        else                 { CP_WAIT(0); }
        __syncthreads();

        uint32_t abuf = sbase + (uint32_t)((kc & 1) * 2 * CHUNK_ELEMS) * 2;
        uint32_t bbuf = abuf + (uint32_t)CHUNK_ELEMS * 2;

        #pragma unroll
        for (int ks = 0; ks < BK / 16; ++ks) {
            uint32_t a[4][4];
            #pragma unroll
            for (int m = 0; m < 4; ++m)
                ldsm_x4(abuf + aLane[m] + ks * 32, a[m][0], a[m][1], a[m][2], a[m][3]);
            uint32_t b[8][2];
            #pragma unroll
            for (int q = 0; q < 4; ++q)
                ldsm_x4(bbuf + bLane[q] + ks * 32,
                        b[2*q][0], b[2*q][1], b[2*q+1][0], b[2*q+1][1]);
            #pragma unroll
            for (int m = 0; m < 4; ++m)
                #pragma unroll
                for (int q = 0; q < 8; ++q)
                    mma_f16acc(acc[m][q], a[m], b[q]);
        }
        __syncthreads();
    }

    // --- epilogue: unpack f16 acc, exp, accumulate row & col sums in one pass ---
    float rs0[4], rs1[4], cs0[8], cs1[8];
    #pragma unroll
    for (int m = 0; m < 4; ++m) { rs0[m] = 0.f; rs1[m] = 0.f; }
    #pragma unroll
    for (int q = 0; q < 8; ++q) { cs0[q] = 0.f; cs1[q] = 0.f; }

    #pragma unroll
    for (int m = 0; m < 4; ++m)
        #pragma unroll
        for (int q = 0; q < 8; ++q) {
            float2 lo = __half22float2(*(__half2*)&acc[m][q][0]);  // row r,   cols c,c+1
            float2 hi = __half22float2(*(__half2*)&acc[m][q][1]);  // row r+8, cols c,c+1
            float e00 = __expf(INV_TEMP * lo.x);
            float e01 = __expf(INV_TEMP * lo.y);
            float e10 = __expf(INV_TEMP * hi.x);
            float e11 = __expf(INV_TEMP * hi.y);
            rs0[m] += e00 + e01;
            rs1[m] += e10 + e11;
            cs0[q] += e00 + e10;
            cs1[q] += e01 + e11;
        }

    float* rowred = (float*)smem;                 // [128][2] by warpN
    float* colred = (float*)smem + 256;           // [128][2] by warpM

    #pragma unroll
    for (int m = 0; m < 4; ++m) {
        float a0 = rs0[m], a1 = rs1[m];
        a0 += __shfl_xor_sync(0xffffffffu, a0, 1);
        a0 += __shfl_xor_sync(0xffffffffu, a0, 2);
        a1 += __shfl_xor_sync(0xffffffffu, a1, 1);
        a1 += __shfl_xor_sync(0xffffffffu, a1, 2);
        if ((lane & 3) == 0) {
            int row = warpM * 64 + m * 16 + (lane >> 2);
            rowred[row * 2 + warpN]       = a0;
            rowred[(row + 8) * 2 + warpN] = a1;
        }
    }

    if (bi != bj) {
        #pragma unroll
        for (int q = 0; q < 8; ++q) {
            float a0 = cs0[q], a1 = cs1[q];
            a0 += __shfl_xor_sync(0xffffffffu, a0, 4);
            a0 += __shfl_xor_sync(0xffffffffu, a0, 8);
            a0 += __shfl_xor_sync(0xffffffffu, a0, 16);
            a1 += __shfl_xor_sync(0xffffffffu, a1, 4);
            a1 += __shfl_xor_sync(0xffffffffu, a1, 8);
            a1 += __shfl_xor_sync(0xffffffffu, a1, 16);
            if (lane < 4) {
                int n = warpN * 64 + q * 8 + lane * 2;
                colred[n * 2 + warpM]       = a0;
                colred[(n + 1) * 2 + warpM] = a1;
            }
        }
    }
    __syncthreads();

    // Transposed partial layout: [row][stripe] (coalesced reads in k_rowloss).
    g_partial[(size_t)(r0 + tid) * NSTRIPE + bj] = rowred[tid * 2] + rowred[tid * 2 + 1];
    if (bi != bj)
        g_partial[(size_t)(c0 + tid) * NSTRIPE + bi] = colred[tid * 2] + colred[tid * 2 + 1];
}

// ---------------------------------------------------------------------------
// Kernel 3: per-row loss + fused mean. Warp per row; stripe sums are
// contiguous (64 floats/row -> float2 per lane). Dots from g_zh fp32-exact.
// ---------------------------------------------------------------------------
__global__ void k_rowloss(float* __restrict__ out) {
    __shared__ float sm[256];
    __shared__ int isLast;
    int tid  = threadIdx.x;
    int row  = blockIdx.x * 8 + (tid >> 5);
    int lane = tid & 31;
    int partner = (row < NB) ? row + NB : row - NB;
    const __half* zr = g_zh + (size_t)row * DD;
    const __half* zp = g_zh + (size_t)partner * DD;

    float ds = 0.f, dp = 0.f;
    {
        uint4 av = *(const uint4*)(zr + lane * 8);   // 8 halves, 16B aligned
        uint4 pv = *(const uint4*)(zp + lane * 8);
        const __half2* ah = (const __half2*)&av;
        const __half2* ph = (const __half2*)&pv;
        #pragma unroll
        for (int h = 0; h < 4; ++h) {
            float2 a2 = __half22float2(ah[h]);
            float2 p2 = __half22float2(ph[h]);
            ds += a2.x * a2.x + a2.y * a2.y;
            dp += a2.x * p2.x + a2.y * p2.y;
        }
    }
    float2 sp = *(const float2*)&g_partial[(size_t)row * NSTRIPE + lane * 2];
    float S = sp.x + sp.y;
    #pragma unroll
    for (int o = 16; o > 0; o >>= 1) {
        ds += __shfl_xor_sync(0xffffffffu, ds, o);
        dp += __shfl_xor_sync(0xffffffffu, dp, o);
        S  += __shfl_xor_sync(0xffffffffu, S,  o);
    }
    if (lane == 0) {
        float ed = __expf(ds * INV_TEMP);
        float ep = __expf(dp * INV_TEMP);
        float en = S - ed;
        g_loss[row] = -logf(ep / (ep + en));
    }
    __threadfence();
    __syncthreads();
    if (tid == 0) {
        int old = atomicAdd(&g_sem, 1);
        isLast = (old == gridDim.x - 1);
    }
    __syncthreads();
    if (isLast) {
        float s = 0.f;
        #pragma unroll
        for (int i = 0; i < 8; ++i) {
            float4 v = *(const float4*)&g_loss[(tid + i * 256) * 4];
            s += v.x + v.y + v.z + v.w;
        }
        sm[tid] = s;
        __syncthreads();
        for (int st = 128; st > 0; st >>= 1) {
            if (tid < st) sm[tid] += sm[tid + st];
            __syncthreads();
        }
        if (tid == 0) { out[0] = sm[0] * (1.0f / (float)N2); g_sem = 0; }
    }
}

extern "C" void kernel_launch(void* const* d_in, const int* in_sizes, int n_in,
                              void* d_out, int out_size) {
    const float* xi = (const float*)d_in[0];
    const float* xj = (const float*)d_in[1];
    float* out = (float*)d_out;

    cudaFuncSetAttribute(k_expsum_mma, cudaFuncAttributeMaxDynamicSharedMemorySize, SMEM_BYTES);

    k_normalize<<<N2 / 8, 256>>>(xi, xj);
    k_expsum_mma<<<NTRI, 128, SMEM_BYTES>>>();
    k_rowloss<<<N2 / 8, 256>>>(out);
}

// round 10
// speedup vs baseline: 1.4221x; 1.0558x over previous
#include <cuda_runtime.h>
#include <cuda_fp16.h>
#include <cstdint>

#define NB 4096
#define N2 8192
#define DD 256
#define INV_TEMP 2.0f
#define EX2_SCALE 2.885390081777927f   // 2 * log2(e)

#define BM 128
#define BN 128
#define BK 64
#define NCHUNK (DD / BK)         // 4 k-chunks
#define NSTRIPE (N2 / BN)        // 64 column stripes
#define NTILE 64
#define NTRI (NTILE * (NTILE + 1) / 2)   // 2080
#define PADK 72                  // f16 elems per smem row (144B)

// Scratch (static device globals — no allocation)
__device__ __half         g_zh[(size_t)N2 * DD];            // normalized rows fp16
__device__ float          g_partial[(size_t)N2 * NSTRIPE];  // [row][stripe] exp-sums (diag masked)
__device__ float          g_pos[N2];                        // positive-pair sims
__device__ float          g_loss[N2];
__device__ int            g_sem;

__device__ __forceinline__ uint32_t smem_u32(const void* p) {
    return (uint32_t)__cvta_generic_to_shared(p);
}

__device__ __forceinline__ void ldsm_x4(uint32_t addr, uint32_t& r0, uint32_t& r1,
                                        uint32_t& r2, uint32_t& r3) {
    asm volatile("ldmatrix.sync.aligned.m8n8.x4.shared.b16 {%0,%1,%2,%3}, [%4];"
                 : "=r"(r0), "=r"(r1), "=r"(r2), "=r"(r3) : "r"(addr));
}

__device__ __forceinline__ void mma_f16acc(uint32_t* d, const uint32_t* a, const uint32_t* b) {
    asm volatile(
        "mma.sync.aligned.m16n8k16.row.col.f16.f16.f16.f16 "
        "{%0,%1}, {%2,%3,%4,%5}, {%6,%7}, {%0,%1};"
        : "+r"(d[0]), "+r"(d[1])
        : "r"(a[0]), "r"(a[1]), "r"(a[2]), "r"(a[3]), "r"(b[0]), "r"(b[1]));
}

__device__ __forceinline__ uint32_t h2ex2(uint32_t x) {
    uint32_t y;
    asm("ex2.approx.f16x2 %0, %1;" : "=r"(y) : "r"(x));
    return y;
}

__device__ __forceinline__ void cp_async16(uint32_t smem_addr, const void* gptr) {
    asm volatile("cp.async.cg.shared.global [%0], [%1], 16;"
                 :: "r"(smem_addr), "l"(gptr) : "memory");
}
#define CP_COMMIT() asm volatile("cp.async.commit_group;" ::: "memory")
#define CP_WAIT(n)  asm volatile("cp.async.wait_group %0;" :: "n"(n) : "memory")

// ---------------------------------------------------------------------------
// Kernel 1: L2-normalize rows of [x_i; x_j] -> g_zh (fp16).
// ---------------------------------------------------------------------------
__global__ void k_normalize(const float* __restrict__ xi, const float* __restrict__ xj) {
    int row  = blockIdx.x * 8 + (threadIdx.x >> 5);
    int lane = threadIdx.x & 31;
    const float* src = (row < NB) ? (xi + (size_t)row * DD)
                                  : (xj + (size_t)(row - NB) * DD);
    float4 v0 = *(const float4*)(src + lane * 4);
    float4 v1 = *(const float4*)(src + 128 + lane * 4);
    float s = v0.x*v0.x + v0.y*v0.y + v0.z*v0.z + v0.w*v0.w
            + v1.x*v1.x + v1.y*v1.y + v1.z*v1.z + v1.w*v1.w;
    #pragma unroll
    for (int o = 16; o > 0; o >>= 1) s += __shfl_xor_sync(0xffffffffu, s, o);
    float inv = 1.0f / fmaxf(sqrtf(s), 1e-12f);
    v0.x *= inv; v0.y *= inv; v0.z *= inv; v0.w *= inv;
    v1.x *= inv; v1.y *= inv; v1.z *= inv; v1.w *= inv;

    __half2 h[4];
    h[0] = __floats2half2_rn(v0.x, v0.y);
    h[1] = __floats2half2_rn(v0.z, v0.w);
    h[2] = __floats2half2_rn(v1.x, v1.y);
    h[3] = __floats2half2_rn(v1.z, v1.w);
    __half* dh = g_zh + (size_t)row * DD;
    *(uint2*)(dh + lane * 4)       = make_uint2(*(uint32_t*)&h[0], *(uint32_t*)&h[1]);
    *(uint2*)(dh + 128 + lane * 4) = make_uint2(*(uint32_t*)&h[2], *(uint32_t*)&h[3]);
}

// ---------------------------------------------------------------------------
// Kernel 2: f16-acc HMMA 128x128 tile, upper triangle, 4 warps x (64x64).
// Diagonal tiles mask sim[r,r] in-tile; tiles bj==bi+32 extract positive
// pairs; off-diagonal tiles emit row AND column exp-sums.
// ---------------------------------------------------------------------------
#define CHUNK_ELEMS (BM * PADK)
#define SMEM_BYTES  (2 * 2 * CHUNK_ELEMS * 2)   // 73728 B

__global__ __launch_bounds__(128, 3) void k_expsum_mma() {
    extern __shared__ __half smem[];
    int tid   = threadIdx.x;
    int lane  = tid & 31;
    int wid   = tid >> 5;          // 0..3
    int warpM = wid >> 1;          // 0..1
    int warpN = wid & 1;           // 0..1

    // Triangular decode: blockIdx.x -> (bi, bj), bi <= bj.
    int idx = blockIdx.x;
    int bi = (int)(64.5f - sqrtf(64.5f * 64.5f - 2.0f * (float)idx));
    while ((bi + 1) * NTILE - ((bi + 1) * bi) / 2 <= idx) ++bi;
    while (bi * NTILE - (bi * (bi - 1)) / 2 > idx) --bi;
    int bj = bi + (idx - (bi * NTILE - (bi * (bi - 1)) / 2));
    int r0 = bi * BM;
    int c0 = bj * BN;

    int lrow = tid >> 3;              // 0..15
    int lcol = (tid & 7) * 8;
    uint32_t sbase = smem_u32(smem);

    auto load_chunk = [&](int kc, int b) {
        uint32_t aoff = sbase + (uint32_t)(b * 2 * CHUNK_ELEMS) * 2;
        uint32_t boff = aoff + (uint32_t)CHUNK_ELEMS * 2;
        const __half* gA = g_zh + (size_t)r0 * DD + kc * BK;
        const __half* gB = g_zh + (size_t)c0 * DD + kc * BK;
        #pragma unroll
        for (int i = 0; i < 8; ++i) {
            int row = lrow + i * 16;
            cp_async16(aoff + (uint32_t)(row * PADK + lcol) * 2,
                       gA + (size_t)row * DD + lcol);
            cp_async16(boff + (uint32_t)(row * PADK + lcol) * 2,
                       gB + (size_t)row * DD + lcol);
        }
        CP_COMMIT();
    };

    uint32_t aLane[4], bLane[4];
    {
        int arow_lane = lane & 15;
        int akh       = lane >> 4;
        #pragma unroll
        for (int m = 0; m < 4; ++m) {
            int row = warpM * 64 + m * 16 + arow_lane;
            aLane[m] = (uint32_t)(row * PADK + akh * 8) * 2;
        }
        int bn  = (lane & 7) | ((lane >> 4) << 3);
        int bkh = (lane >> 3) & 1;
        #pragma unroll
        for (int q = 0; q < 4; ++q) {
            int n = warpN * 64 + q * 16 + bn;
            bLane[q] = (uint32_t)(n * PADK + bkh * 8) * 2;
        }
    }

    uint32_t acc[4][8][2];
    #pragma unroll
    for (int m = 0; m < 4; ++m)
        #pragma unroll
        for (int q = 0; q < 8; ++q) { acc[m][q][0] = 0u; acc[m][q][1] = 0u; }

    load_chunk(0, 0);

    #pragma unroll
    for (int kc = 0; kc < NCHUNK; ++kc) {
        if (kc + 1 < NCHUNK) { load_chunk(kc + 1, (kc + 1) & 1); CP_WAIT(1); }
        else                 { CP_WAIT(0); }
        __syncthreads();

        uint32_t abuf = sbase + (uint32_t)((kc & 1) * 2 * CHUNK_ELEMS) * 2;
        uint32_t bbuf = abuf + (uint32_t)CHUNK_ELEMS * 2;

        #pragma unroll
        for (int ks = 0; ks < BK / 16; ++ks) {
            uint32_t a[4][4];
            #pragma unroll
            for (int m = 0; m < 4; ++m)
                ldsm_x4(abuf + aLane[m] + ks * 32, a[m][0], a[m][1], a[m][2], a[m][3]);
            uint32_t b[8][2];
            #pragma unroll
            for (int q = 0; q < 4; ++q)
                ldsm_x4(bbuf + bLane[q] + ks * 32,
                        b[2*q][0], b[2*q][1], b[2*q+1][0], b[2*q+1][1]);
            #pragma unroll
            for (int m = 0; m < 4; ++m)
                #pragma unroll
                for (int q = 0; q < 8; ++q)
                    mma_f16acc(acc[m][q], a[m], b[q]);
        }
        __syncthreads();
    }

    // Per-thread fragment coordinates.
    int r_base = warpM * 64 + (lane >> 2);        // + m*16 + h*8
    int c_base = warpN * 64 + (lane & 3) * 2;     // + q*8 + o

    // --- positive-pair extraction: tiles with c0 == r0 + NB have pos on the
    //     local diagonal. Store sim (pre-exp, fp32) for both partner rows.
    if (bj == bi + 32) {
        #pragma unroll
        for (int m = 0; m < 4; ++m)
            #pragma unroll
            for (int q = 0; q < 8; ++q) {
                float2 lo = __half22float2(*(__half2*)&acc[m][q][0]);
                float2 hi = __half22float2(*(__half2*)&acc[m][q][1]);
                int rl0 = r_base + m * 16, cl = c_base + q * 8;
                if (rl0 == cl)         { g_pos[r0 + rl0] = lo.x;     g_pos[r0 + rl0 + NB] = lo.x; }
                if (rl0 == cl + 1)     { g_pos[r0 + rl0] = lo.y;     g_pos[r0 + rl0 + NB] = lo.y; }
                if (rl0 + 8 == cl)     { g_pos[r0 + rl0 + 8] = hi.x; g_pos[r0 + rl0 + 8 + NB] = hi.x; }
                if (rl0 + 8 == cl + 1) { g_pos[r0 + rl0 + 8] = hi.y; g_pos[r0 + rl0 + 8 + NB] = hi.y; }
            }
    }

    // --- exp via f16x2 (ex2.approx), then accumulate row & col sums in fp32 ---
    bool isDiag = (bi == bj);
    const __half2 cmul = __float2half2_rn(EX2_SCALE);
    uint32_t cmul_u = *(const uint32_t*)&cmul;

    float rs0[4], rs1[4], cs0[8], cs1[8];
    #pragma unroll
    for (int m = 0; m < 4; ++m) { rs0[m] = 0.f; rs1[m] = 0.f; }
    #pragma unroll
    for (int q = 0; q < 8; ++q) { cs0[q] = 0.f; cs1[q] = 0.f; }

    #pragma unroll
    for (int m = 0; m < 4; ++m)
        #pragma unroll
        for (int q = 0; q < 8; ++q) {
            __half2 s0 = __hmul2(*(__half2*)&acc[m][q][0], *(const __half2*)&cmul_u);
            __half2 s1 = __hmul2(*(__half2*)&acc[m][q][1], *(const __half2*)&cmul_u);
            uint32_t e0u = h2ex2(*(uint32_t*)&s0);
            uint32_t e1u = h2ex2(*(uint32_t*)&s1);
            float2 e0 = __half22float2(*(__half2*)&e0u);   // row r,   cols c,c+1
            float2 e1 = __half22float2(*(__half2*)&e1u);   // row r+8, cols c,c+1
            if (isDiag) {
                int rl0 = r_base + m * 16, cl = c_base + q * 8;
                if (rl0 == cl)         e0.x = 0.f;
                if (rl0 == cl + 1)     e0.y = 0.f;
                if (rl0 + 8 == cl)     e1.x = 0.f;
                if (rl0 + 8 == cl + 1) e1.y = 0.f;
            }
            rs0[m] += e0.x + e0.y;
            rs1[m] += e1.x + e1.y;
            cs0[q] += e0.x + e1.x;
            cs1[q] += e0.y + e1.y;
        }

    float* rowred = (float*)smem;                 // [128][2] by warpN
    float* colred = (float*)smem + 256;           // [128][2] by warpM

    #pragma unroll
    for (int m = 0; m < 4; ++m) {
        float a0 = rs0[m], a1 = rs1[m];
        a0 += __shfl_xor_sync(0xffffffffu, a0, 1);
        a0 += __shfl_xor_sync(0xffffffffu, a0, 2);
        a1 += __shfl_xor_sync(0xffffffffu, a1, 1);
        a1 += __shfl_xor_sync(0xffffffffu, a1, 2);
        if ((lane & 3) == 0) {
            int row = warpM * 64 + m * 16 + (lane >> 2);
            rowred[row * 2 + warpN]       = a0;
            rowred[(row + 8) * 2 + warpN] = a1;
        }
    }

    if (!isDiag) {
        #pragma unroll
        for (int q = 0; q < 8; ++q) {
            float a0 = cs0[q], a1 = cs1[q];
            a0 += __shfl_xor_sync(0xffffffffu, a0, 4);
            a0 += __shfl_xor_sync(0xffffffffu, a0, 8);
            a0 += __shfl_xor_sync(0xffffffffu, a0, 16);
            a1 += __shfl_xor_sync(0xffffffffu, a1, 4);
            a1 += __shfl_xor_sync(0xffffffffu, a1, 8);
            a1 += __shfl_xor_sync(0xffffffffu, a1, 16);
            if (lane < 4) {
                int n = warpN * 64 + q * 8 + lane * 2;
                colred[n * 2 + warpM]       = a0;
                colred[(n + 1) * 2 + warpM] = a1;
            }
        }
    }
    __syncthreads();

    // Transposed partial layout: [row][stripe].
    g_partial[(size_t)(r0 + tid) * NSTRIPE + bj] = rowred[tid * 2] + rowred[tid * 2 + 1];
    if (!isDiag)
        g_partial[(size_t)(c0 + tid) * NSTRIPE + bi] = colred[tid * 2] + colred[tid * 2 + 1];
}

// ---------------------------------------------------------------------------
// Kernel 3: per-row loss + fused mean. Partials already exclude the diagonal;
// positive pair is precomputed. Warp per row, coalesced partial reads.
// ---------------------------------------------------------------------------
__global__ void k_rowloss(float* __restrict__ out) {
    __shared__ float sm[256];
    __shared__ int isLast;
    int tid  = threadIdx.x;
    int row  = blockIdx.x * 8 + (tid >> 5);
    int lane = tid & 31;

    float2 sp = *(const float2*)&g_partial[(size_t)row * NSTRIPE + lane * 2];
    float S = sp.x + sp.y;
    #pragma unroll
    for (int o = 16; o > 0; o >>= 1) S += __shfl_xor_sync(0xffffffffu, S, o);

    if (lane == 0) {
        float ep = __expf(INV_TEMP * g_pos[row]);
        g_loss[row] = -logf(ep / (ep + S));
    }
    __threadfence();
    __syncthreads();
    if (tid == 0) {
        int old = atomicAdd(&g_sem, 1);
        isLast = (old == gridDim.x - 1);
    }
    __syncthreads();
    if (isLast) {
        float s = 0.f;
        #pragma unroll
        for (int i = 0; i < 8; ++i) {
            float4 v = *(const float4*)&g_loss[(tid + i * 256) * 4];
            s += v.x + v.y + v.z + v.w;
        }
        sm[tid] = s;
        __syncthreads();
        for (int st = 128; st > 0; st >>= 1) {
            if (tid < st) sm[tid] += sm[tid + st];
            __syncthreads();
        }
        if (tid == 0) { out[0] = sm[0] * (1.0f / (float)N2); g_sem = 0; }
    }
}

extern "C" void kernel_launch(void* const* d_in, const int* in_sizes, int n_in,
                              void* d_out, int out_size) {
    const float* xi = (const float*)d_in[0];
    const float* xj = (const float*)d_in[1];
    float* out = (float*)d_out;

    cudaFuncSetAttribute(k_expsum_mma, cudaFuncAttributeMaxDynamicSharedMemorySize, SMEM_BYTES);

    k_normalize<<<N2 / 8, 256>>>(xi, xj);
    k_expsum_mma<<<NTRI, 128, SMEM_BYTES>>>();
    k_rowloss<<<N2 / 8, 256>>>(out);
}

// round 11
// speedup vs baseline: 1.4499x; 1.0196x over previous
#include <cuda_runtime.h>
#include <cuda_fp16.h>
#include <cstdint>

#define NB 4096
#define N2 8192
#define DD 256
#define INV_TEMP 2.0f
#define EX2_SCALE 2.885390081777927f   // 2 * log2(e)

#define BM 128
#define BN 128
#define BK 64
#define NCHUNK (DD / BK)         // 4 k-chunks
#define NSTRIPE (N2 / BN)        // 64 column stripes
#define NTILE 64
#define NTRI (NTILE * (NTILE + 1) / 2)   // 2080
#define PADK 72                  // f16 elems per smem row (144B)

// Scratch (static device globals — no allocation)
__device__ __half         g_zh[(size_t)N2 * DD];            // normalized rows fp16
__device__ float          g_partial[(size_t)NSTRIPE * N2];  // [stripe][row] exp-sums (diag masked)
__device__ float          g_pos[N2];                        // positive-pair sims
__device__ float          g_loss[N2];
__device__ int            g_sem;

__device__ __forceinline__ uint32_t smem_u32(const void* p) {
    return (uint32_t)__cvta_generic_to_shared(p);
}

__device__ __forceinline__ void ldsm_x4(uint32_t addr, uint32_t& r0, uint32_t& r1,
                                        uint32_t& r2, uint32_t& r3) {
    asm volatile("ldmatrix.sync.aligned.m8n8.x4.shared.b16 {%0,%1,%2,%3}, [%4];"
                 : "=r"(r0), "=r"(r1), "=r"(r2), "=r"(r3) : "r"(addr));
}

__device__ __forceinline__ void mma_f16acc(uint32_t* d, const uint32_t* a, const uint32_t* b) {
    asm volatile(
        "mma.sync.aligned.m16n8k16.row.col.f16.f16.f16.f16 "
        "{%0,%1}, {%2,%3,%4,%5}, {%6,%7}, {%0,%1};"
        : "+r"(d[0]), "+r"(d[1])
        : "r"(a[0]), "r"(a[1]), "r"(a[2]), "r"(a[3]), "r"(b[0]), "r"(b[1]));
}

__device__ __forceinline__ uint32_t h2ex2(uint32_t x) {
    uint32_t y;
    asm("ex2.approx.f16x2 %0, %1;" : "=r"(y) : "r"(x));
    return y;
}
__device__ __forceinline__ uint32_t h2mul(uint32_t a, uint32_t b) {
    __half2 r = __hmul2(*(__half2*)&a, *(__half2*)&b);
    return *(uint32_t*)&r;
}
__device__ __forceinline__ uint32_t h2add(uint32_t a, uint32_t b) {
    __half2 r = __hadd2(*(__half2*)&a, *(__half2*)&b);
    return *(uint32_t*)&r;
}

__device__ __forceinline__ void cp_async16(uint32_t smem_addr, const void* gptr) {
    asm volatile("cp.async.cg.shared.global [%0], [%1], 16;"
                 :: "r"(smem_addr), "l"(gptr) : "memory");
}
#define CP_COMMIT() asm volatile("cp.async.commit_group;" ::: "memory")
#define CP_WAIT(n)  asm volatile("cp.async.wait_group %0;" :: "n"(n) : "memory")

// ---------------------------------------------------------------------------
// Kernel 1: L2-normalize. One warp handles rows (w, w+NB): two independent
// reduction chains for ILP. 512 blocks x 256 threads.
// ---------------------------------------------------------------------------
__global__ void k_normalize(const float* __restrict__ xi, const float* __restrict__ xj) {
    int w    = blockIdx.x * 8 + (threadIdx.x >> 5);   // 0..4095
    int lane = threadIdx.x & 31;
    const float* sa = xi + (size_t)w * DD;
    const float* sb = xj + (size_t)w * DD;
    float4 a0 = *(const float4*)(sa + lane * 4);
    float4 a1 = *(const float4*)(sa + 128 + lane * 4);
    float4 b0 = *(const float4*)(sb + lane * 4);
    float4 b1 = *(const float4*)(sb + 128 + lane * 4);
    float s_a = a0.x*a0.x + a0.y*a0.y + a0.z*a0.z + a0.w*a0.w
              + a1.x*a1.x + a1.y*a1.y + a1.z*a1.z + a1.w*a1.w;
    float s_b = b0.x*b0.x + b0.y*b0.y + b0.z*b0.z + b0.w*b0.w
              + b1.x*b1.x + b1.y*b1.y + b1.z*b1.z + b1.w*b1.w;
    #pragma unroll
    for (int o = 16; o > 0; o >>= 1) {
        s_a += __shfl_xor_sync(0xffffffffu, s_a, o);
        s_b += __shfl_xor_sync(0xffffffffu, s_b, o);
    }
    float ia = 1.0f / fmaxf(sqrtf(s_a), 1e-12f);
    float ib = 1.0f / fmaxf(sqrtf(s_b), 1e-12f);

    __half2 h[4];
    h[0] = __floats2half2_rn(a0.x * ia, a0.y * ia);
    h[1] = __floats2half2_rn(a0.z * ia, a0.w * ia);
    h[2] = __floats2half2_rn(a1.x * ia, a1.y * ia);
    h[3] = __floats2half2_rn(a1.z * ia, a1.w * ia);
    __half* da = g_zh + (size_t)w * DD;
    *(uint2*)(da + lane * 4)       = make_uint2(*(uint32_t*)&h[0], *(uint32_t*)&h[1]);
    *(uint2*)(da + 128 + lane * 4) = make_uint2(*(uint32_t*)&h[2], *(uint32_t*)&h[3]);

    h[0] = __floats2half2_rn(b0.x * ib, b0.y * ib);
    h[1] = __floats2half2_rn(b0.z * ib, b0.w * ib);
    h[2] = __floats2half2_rn(b1.x * ib, b1.y * ib);
    h[3] = __floats2half2_rn(b1.z * ib, b1.w * ib);
    __half* db = g_zh + (size_t)(w + NB) * DD;
    *(uint2*)(db + lane * 4)       = make_uint2(*(uint32_t*)&h[0], *(uint32_t*)&h[1]);
    *(uint2*)(db + 128 + lane * 4) = make_uint2(*(uint32_t*)&h[2], *(uint32_t*)&h[3]);
}

// ---------------------------------------------------------------------------
// Kernel 2: f16-acc HMMA 128x128 tile, upper triangle, 4 warps x (64x64).
// Epilogue: f16x2 exp + HADD2 partial sums; f32 only for cross-lane reduce.
// ---------------------------------------------------------------------------
#define CHUNK_ELEMS (BM * PADK)
#define SMEM_BYTES  (2 * 2 * CHUNK_ELEMS * 2)   // 73728 B

__global__ __launch_bounds__(128, 3) void k_expsum_mma() {
    extern __shared__ __half smem[];
    int tid   = threadIdx.x;
    int lane  = tid & 31;
    int wid   = tid >> 5;          // 0..3
    int warpM = wid >> 1;          // 0..1
    int warpN = wid & 1;           // 0..1

    // Triangular decode: blockIdx.x -> (bi, bj), bi <= bj.
    int idx = blockIdx.x;
    int bi = (int)(64.5f - sqrtf(64.5f * 64.5f - 2.0f * (float)idx));
    while ((bi + 1) * NTILE - ((bi + 1) * bi) / 2 <= idx) ++bi;
    while (bi * NTILE - (bi * (bi - 1)) / 2 > idx) --bi;
    int bj = bi + (idx - (bi * NTILE - (bi * (bi - 1)) / 2));
    int r0 = bi * BM;
    int c0 = bj * BN;

    int lrow = tid >> 3;              // 0..15
    int lcol = (tid & 7) * 8;
    uint32_t sbase = smem_u32(smem);

    auto load_chunk = [&](int kc, int b) {
        uint32_t aoff = sbase + (uint32_t)(b * 2 * CHUNK_ELEMS) * 2;
        uint32_t boff = aoff + (uint32_t)CHUNK_ELEMS * 2;
        const __half* gA = g_zh + (size_t)r0 * DD + kc * BK;
        const __half* gB = g_zh + (size_t)c0 * DD + kc * BK;
        #pragma unroll
        for (int i = 0; i < 8; ++i) {
            int row = lrow + i * 16;
            cp_async16(aoff + (uint32_t)(row * PADK + lcol) * 2,
                       gA + (size_t)row * DD + lcol);
            cp_async16(boff + (uint32_t)(row * PADK + lcol) * 2,
                       gB + (size_t)row * DD + lcol);
        }
        CP_COMMIT();
    };

    uint32_t aLane[4], bLane[4];
    {
        int arow_lane = lane & 15;
        int akh       = lane >> 4;
        #pragma unroll
        for (int m = 0; m < 4; ++m) {
            int row = warpM * 64 + m * 16 + arow_lane;
            aLane[m] = (uint32_t)(row * PADK + akh * 8) * 2;
        }
        int bn  = (lane & 7) | ((lane >> 4) << 3);
        int bkh = (lane >> 3) & 1;
        #pragma unroll
        for (int q = 0; q < 4; ++q) {
            int n = warpN * 64 + q * 16 + bn;
            bLane[q] = (uint32_t)(n * PADK + bkh * 8) * 2;
        }
    }

    uint32_t acc[4][8][2];
    #pragma unroll
    for (int m = 0; m < 4; ++m)
        #pragma unroll
        for (int q = 0; q < 8; ++q) { acc[m][q][0] = 0u; acc[m][q][1] = 0u; }

    load_chunk(0, 0);

    #pragma unroll
    for (int kc = 0; kc < NCHUNK; ++kc) {
        if (kc + 1 < NCHUNK) { load_chunk(kc + 1, (kc + 1) & 1); CP_WAIT(1); }
        else                 { CP_WAIT(0); }
        __syncthreads();

        uint32_t abuf = sbase + (uint32_t)((kc & 1) * 2 * CHUNK_ELEMS) * 2;
        uint32_t bbuf = abuf + (uint32_t)CHUNK_ELEMS * 2;

        #pragma unroll
        for (int ks = 0; ks < BK / 16; ++ks) {
            uint32_t a[4][4];
            #pragma unroll
            for (int m = 0; m < 4; ++m)
                ldsm_x4(abuf + aLane[m] + ks * 32, a[m][0], a[m][1], a[m][2], a[m][3]);
            uint32_t b[8][2];
            #pragma unroll
            for (int q = 0; q < 4; ++q)
                ldsm_x4(bbuf + bLane[q] + ks * 32,
                        b[2*q][0], b[2*q][1], b[2*q+1][0], b[2*q+1][1]);
            #pragma unroll
            for (int m = 0; m < 4; ++m)
                #pragma unroll
                for (int q = 0; q < 8; ++q)
                    mma_f16acc(acc[m][q], a[m], b[q]);
        }
        __syncthreads();
    }

    // Per-thread fragment coordinates.
    int r_base = warpM * 64 + (lane >> 2);        // + m*16 + h*8
    int c_base = warpN * 64 + (lane & 3) * 2;     // + q*8 + o

    // --- positive-pair extraction (tiles with c0 == r0 + NB) ---
    if (bj == bi + 32) {
        #pragma unroll
        for (int m = 0; m < 4; ++m)
            #pragma unroll
            for (int q = 0; q < 8; ++q) {
                float2 lo = __half22float2(*(__half2*)&acc[m][q][0]);
                float2 hi = __half22float2(*(__half2*)&acc[m][q][1]);
                int rl0 = r_base + m * 16, cl = c_base + q * 8;
                if (rl0 == cl)         { g_pos[r0 + rl0] = lo.x;     g_pos[r0 + rl0 + NB] = lo.x; }
                if (rl0 == cl + 1)     { g_pos[r0 + rl0] = lo.y;     g_pos[r0 + rl0 + NB] = lo.y; }
                if (rl0 + 8 == cl)     { g_pos[r0 + rl0 + 8] = hi.x; g_pos[r0 + rl0 + 8 + NB] = hi.x; }
                if (rl0 + 8 == cl + 1) { g_pos[r0 + rl0 + 8] = hi.y; g_pos[r0 + rl0 + 8 + NB] = hi.y; }
            }
    }

    // --- exp (f16x2) + HADD2 partial sums ---
    bool isDiag = (bi == bj);
    const __half2 cmulh = __float2half2_rn(EX2_SCALE);
    uint32_t cmul_u = *(const uint32_t*)&cmulh;

    uint32_t racc0[4], racc1[4], cacc[8];
    #pragma unroll
    for (int m = 0; m < 4; ++m) { racc0[m] = 0u; racc1[m] = 0u; }
    #pragma unroll
    for (int q = 0; q < 8; ++q) cacc[q] = 0u;

    #pragma unroll
    for (int m = 0; m < 4; ++m)
        #pragma unroll
        for (int q = 0; q < 8; ++q) {
            uint32_t e0u = h2ex2(h2mul(acc[m][q][0], cmul_u));   // row r,   cols c,c+1
            uint32_t e1u = h2ex2(h2mul(acc[m][q][1], cmul_u));   // row r+8, cols c,c+1
            if (isDiag) {
                int rl0 = r_base + m * 16, cl = c_base + q * 8;
                if (rl0 == cl)         e0u &= 0xFFFF0000u;
                if (rl0 == cl + 1)     e0u &= 0x0000FFFFu;
                if (rl0 + 8 == cl)     e1u &= 0xFFFF0000u;
                if (rl0 + 8 == cl + 1) e1u &= 0x0000FFFFu;
            }
            racc0[m] = h2add(racc0[m], e0u);
            racc1[m] = h2add(racc1[m], e1u);
            cacc[q]  = h2add(cacc[q], h2add(e0u, e1u));
        }

    float* rowred = (float*)smem;                 // [128][2] by warpN
    float* colred = (float*)smem + 256;           // [128][2] by warpM

    #pragma unroll
    for (int m = 0; m < 4; ++m) {
        float2 f0 = __half22float2(*(__half2*)&racc0[m]);
        float2 f1 = __half22float2(*(__half2*)&racc1[m]);
        float a0 = f0.x + f0.y;
        float a1 = f1.x + f1.y;
        a0 += __shfl_xor_sync(0xffffffffu, a0, 1);
        a0 += __shfl_xor_sync(0xffffffffu, a0, 2);
        a1 += __shfl_xor_sync(0xffffffffu, a1, 1);
        a1 += __shfl_xor_sync(0xffffffffu, a1, 2);
        if ((lane & 3) == 0) {
            int row = warpM * 64 + m * 16 + (lane >> 2);
            rowred[row * 2 + warpN]       = a0;
            rowred[(row + 8) * 2 + warpN] = a1;
        }
    }

    if (!isDiag) {
        #pragma unroll
        for (int q = 0; q < 8; ++q) {
            float2 fc = __half22float2(*(__half2*)&cacc[q]);
            float a0 = fc.x, a1 = fc.y;
            a0 += __shfl_xor_sync(0xffffffffu, a0, 4);
            a0 += __shfl_xor_sync(0xffffffffu, a0, 8);
            a0 += __shfl_xor_sync(0xffffffffu, a0, 16);
            a1 += __shfl_xor_sync(0xffffffffu, a1, 4);
            a1 += __shfl_xor_sync(0xffffffffu, a1, 8);
            a1 += __shfl_xor_sync(0xffffffffu, a1, 16);
            if (lane < 4) {
                int n = warpN * 64 + q * 8 + lane * 2;
                colred[n * 2 + warpM]       = a0;
                colred[(n + 1) * 2 + warpM] = a1;
            }
        }
    }
    __syncthreads();

    // [stripe][row] layout: both stores fully coalesced.
    g_partial[(size_t)bj * N2 + r0 + tid] = rowred[tid * 2] + rowred[tid * 2 + 1];
    if (!isDiag)
        g_partial[(size_t)bi * N2 + c0 + tid] = colred[tid * 2] + colred[tid * 2 + 1];
}

// ---------------------------------------------------------------------------
// Kernel 3: per-row loss + fused mean. Block covers 8 rows; partials loaded
// coalesced ([stripe][row]) then transposed through smem.
// ---------------------------------------------------------------------------
__global__ void k_rowloss(float* __restrict__ out) {
    __shared__ float st[8][68];
    __shared__ float sm[256];
    __shared__ int isLast;
    int tid = threadIdx.x;
    int r0  = blockIdx.x * 8;

    // Coalesced load: 4 threads x float2 cover 8 rows of one stripe.
    {
        int s  = tid >> 2;            // stripe 0..63
        int ro = (tid & 3) * 2;       // row offset 0,2,4,6
        float2 v = *(const float2*)&g_partial[(size_t)s * N2 + r0 + ro];
        st[ro][s]     = v.x;
        st[ro + 1][s] = v.y;
    }
    __syncthreads();

    int w    = tid >> 5;              // row within block
    int lane = tid & 31;
    float S = st[w][lane] + st[w][lane + 32];
    #pragma unroll
    for (int o = 16; o > 0; o >>= 1) S += __shfl_xor_sync(0xffffffffu, S, o);

    if (lane == 0) {
        float ep = __expf(INV_TEMP * g_pos[r0 + w]);
        g_loss[r0 + w] = -logf(ep / (ep + S));
    }
    __threadfence();
    __syncthreads();
    if (tid == 0) {
        int old = atomicAdd(&g_sem, 1);
        isLast = (old == gridDim.x - 1);
    }
    __syncthreads();
    if (isLast) {
        float s = 0.f;
        #pragma unroll
        for (int i = 0; i < 8; ++i) {
            float4 v = *(const float4*)&g_loss[(tid + i * 256) * 4];
            s += v.x + v.y + v.z + v.w;
        }
        sm[tid] = s;
        __syncthreads();
        for (int stp = 128; stp > 0; stp >>= 1) {
            if (tid < stp) sm[tid] += sm[tid + stp];
            __syncthreads();
        }
        if (tid == 0) { out[0] = sm[0] * (1.0f / (float)N2); g_sem = 0; }
    }
}

extern "C" void kernel_launch(void* const* d_in, const int* in_sizes, int n_in,
                              void* d_out, int out_size) {
    const float* xi = (const float*)d_in[0];
    const float* xj = (const float*)d_in[1];
    float* out = (float*)d_out;

    cudaFuncSetAttribute(k_expsum_mma, cudaFuncAttributeMaxDynamicSharedMemorySize, SMEM_BYTES);

    k_normalize<<<512, 256>>>(xi, xj);
    k_expsum_mma<<<NTRI, 128, SMEM_BYTES>>>();
    k_rowloss<<<N2 / 8, 256>>>(out);
}